// round 11
// baseline (speedup 1.0000x reference)
#include <cuda_runtime.h>
#include <cuda_bf16.h>
#include <cstdint>

// Problem shapes (fixed for this dataset)
#define TOKENS 8192
#define DIN    4096
#define DOUT   4096

// GEMM tiling (bf16 HMMA path, baseline PTX only: cp.async + ldmatrix + mma.sync)
#define BM 128
#define BN 256
#define BK 64                        // 64 bf16 = one 128B SW128 row
#define STAGES 4
#define KCH (DIN / BK)               // 64 k-chunks per tile
#define NTILES ((TOKENS / BM) * (DOUT / BN))   // 1024
#define NSM 148

#define A_BYTES (BM * 128)           // 16384
#define B_BYTES (BN * 128)           // 32768
#define STAGE_BYTES (A_BYTES + B_BYTES)  // 49152
#define SMEM_TOTAL (STAGES * STAGE_BYTES)  // 196608

// ---------------- device-global scratch (no allocation allowed) ----------------
__device__ __align__(256) __nv_bfloat16 g_qx[(size_t)TOKENS * DIN];
__device__ __align__(256) __nv_bfloat16 g_qw[(size_t)DOUT * DIN];
__device__ float g_sx[TOKENS];
__device__ float g_sw[DOUT];

// ---------------- PTX helpers (all baseline, compile under compute_103) --------
__device__ __forceinline__ uint32_t smem_u32(const void* p) {
    uint32_t a;
    asm("{ .reg .u64 t; cvta.to.shared.u64 t, %1; cvt.u32.u64 %0, t; }" : "=r"(a) : "l"(p));
    return a;
}

#define CP16(dst, src) \
    asm volatile("cp.async.cg.shared.global [%0], [%1], 16;\n" \
                 :: "r"(dst), "l"(__cvta_generic_to_global(src)))
#define CP_COMMIT() asm volatile("cp.async.commit_group;\n" ::: "memory")
#define CP_WAIT2()  asm volatile("cp.async.wait_group 2;\n" ::: "memory")

#define LDSM4(r, addr) \
    asm volatile("ldmatrix.sync.aligned.m8n8.x4.shared.b16 {%0,%1,%2,%3}, [%4];" \
                 : "=r"((r)[0]), "=r"((r)[1]), "=r"((r)[2]), "=r"((r)[3]) : "r"(addr))

// bf16 x bf16 -> f32 accumulate (HMMA hardware fallback path on sm_103)
#define HMMA(d, a, b0, b1) \
    asm volatile("mma.sync.aligned.m16n8k16.row.col.f32.bf16.bf16.f32 " \
                 "{%0,%1,%2,%3}, {%4,%5,%6,%7}, {%8,%9}, {%0,%1,%2,%3};" \
                 : "+f"((d)[0]), "+f"((d)[1]), "+f"((d)[2]), "+f"((d)[3]) \
                 : "r"((a)[0]), "r"((a)[1]), "r"((a)[2]), "r"((a)[3]), \
                   "r"(b0), "r"(b1))

// ---------------- quantize (fused x + W): per-row absmax -> bf16 ints + scale --
// grid = TOKENS + DOUT; 256 threads/row; thread t owns 16 consecutive floats.
__global__ void __launch_bounds__(256) quant_kernel(const float* __restrict__ x,
                                                    const float* __restrict__ W) {
    const int blk = blockIdx.x;
    const bool isW = (blk >= TOKENS);
    const int row = isW ? (blk - TOKENS) : blk;
    const float* in = isW ? W : x;
    const int tid = threadIdx.x;
    const float4* inr = reinterpret_cast<const float4*>(in + (size_t)row * DIN) + tid * 4;

    float4 v[4];
    float amax = 0.f;
#pragma unroll
    for (int i = 0; i < 4; i++) {
        v[i] = inr[i];
        amax = fmaxf(amax, fmaxf(fmaxf(fabsf(v[i].x), fabsf(v[i].y)),
                                 fmaxf(fabsf(v[i].z), fabsf(v[i].w))));
    }
#pragma unroll
    for (int o = 16; o; o >>= 1) amax = fmaxf(amax, __shfl_xor_sync(0xffffffffu, amax, o));

    __shared__ float red[8];
    __shared__ float s_bcast;
    if ((tid & 31) == 0) red[tid >> 5] = amax;
    __syncthreads();
    if (tid < 8) {
        float a = red[tid];
#pragma unroll
        for (int o = 4; o; o >>= 1) a = fmaxf(a, __shfl_xor_sync(0xffu, a, o));
        // IEEE ops to bit-match jnp: max(absmax,1e-8)/127
        if (tid == 0) s_bcast = __fdiv_rn(fmaxf(a, 1e-8f), 127.0f);
    }
    __syncthreads();
    const float s = s_bcast;

    __nv_bfloat16* q = isW ? g_qw : g_qx;
    float* sc = isW ? g_sw : g_sx;
    if (tid == 0) sc[row] = s;

    // quantized values are integers in [-127,127]: exact in bf16
    __nv_bfloat162* qp = reinterpret_cast<__nv_bfloat162*>(q + (size_t)row * DIN);
#pragma unroll
    for (int i = 0; i < 4; i++) {
        float4 t = v[i];
        // __fdiv_rn + rintf (round-half-even) matches jnp.round(a/scale) exactly
        float q0 = fminf(fmaxf(rintf(__fdiv_rn(t.x, s)), -127.f), 127.f);
        float q1 = fminf(fmaxf(rintf(__fdiv_rn(t.y, s)), -127.f), 127.f);
        float q2 = fminf(fmaxf(rintf(__fdiv_rn(t.z, s)), -127.f), 127.f);
        float q3 = fminf(fmaxf(rintf(__fdiv_rn(t.w, s)), -127.f), 127.f);
        const int p = tid * 8 + i * 2;
        qp[p]     = __floats2bfloat162_rn(q0, q1);
        qp[p + 1] = __floats2bfloat162_rn(q2, q3);
    }
}

// ---------------- GEMM: out[t,o] = (qx . qw) * sx[t]*sw[o] + bias[o] -----------
// PERSISTENT: grid=148, each CTA walks tiles t = cta, cta+148, ... over a flat
// chunk counter (tile*64 + kiter). The 4-stage cp.async ring streams straight
// across tile boundaries, so each tile's epilogue overlaps the next tile's
// global->smem fills, and only the very first prologue is exposed.
// 8 warps as 2(m) x 4(n); warp tile 64x64; mma m16n8k16 bf16 -> f32.
__global__ void __launch_bounds__(256, 1)
gemm_kernel(const float* __restrict__ bias, float* __restrict__ out) {
    extern __shared__ char smem[];
    const uint32_t sb = smem_u32(smem);
    const int tid = threadIdx.x;
    const int wid = tid >> 5;
    const int L   = tid & 31;
    const int cta = blockIdx.x;

    const int ntiles  = (NTILES - cta + NSM - 1) / NSM;   // 6 or 7
    const int nchunks = ntiles * KCH;

    // fill ring slot (j & 3) with chunk j: tile cta + (j>>6)*148, k-iter j&63
    auto load_chunk = [&](int j) {
        const int t  = cta + (j >> 6) * NSM;
        const int kt = j & (KCH - 1);
        const __nv_bfloat16* aT = g_qx + ((size_t)(t >> 4) * BM) * DIN + kt * BK;
        const __nv_bfloat16* bT = g_qw + ((size_t)(t & 15) * BN) * DIN + kt * BK;
        uint32_t ab = sb + (j & 3) * STAGE_BYTES;
        uint32_t bb = ab + A_BYTES;
#pragma unroll
        for (int i = 0; i < 4; i++) {
            int c = tid + i * 256;
            int row = c >> 3, ko = c & 7;
            uint32_t off = row * 128 + ((ko * 16) ^ ((row & 7) * 16));   // SW128
            CP16(ab + off, aT + (size_t)row * DIN + ko * 8);
        }
#pragma unroll
        for (int i = 0; i < 8; i++) {
            int c = tid + i * 256;
            int row = c >> 3, ko = c & 7;
            uint32_t off = row * 128 + ((ko * 16) ^ ((row & 7) * 16));
            CP16(bb + off, bT + (size_t)row * DIN + ko * 8);
        }
    };

    // warp layout + per-lane ldmatrix address constants
    const int wm = wid >> 2;             // 0..1 -> 64 M rows
    const int wn = wid & 3;              // 0..3 -> 64 N cols
    const int lr = L & 7;
    const int cRow = lr * 16;            // swizzle XOR term ((row&7)*16)
    const int akh = ((L >> 4) & 1) * 16; // A k-half select (matrices 2,3)
    const int bkh = ((L >> 3) & 1) * 16; // B k-half select (matrices 1,3)

    uint32_t aRow[4], bRowP[4];
#pragma unroll
    for (int mf = 0; mf < 4; mf++)
        aRow[mf] = (uint32_t)(wm * 64 + mf * 16 + lr + ((L >> 3) & 1) * 8) * 128;
    // B x4 pairing: lanes 0-15 -> n8 block 2p (k lo/hi), lanes 16-31 -> block 2p+1
#pragma unroll
    for (int p = 0; p < 4; p++)
        bRowP[p] = (uint32_t)(wn * 64 + p * 16 + ((L >> 4) & 1) * 8 + lr) * 128;

    float acc[4][8][4];
#pragma unroll
    for (int mf = 0; mf < 4; mf++)
#pragma unroll
        for (int nf = 0; nf < 8; nf++)
#pragma unroll
            for (int j = 0; j < 4; j++) acc[mf][nf][j] = 0.f;

    // prologue: fill chunks 0..2, ensure chunk 0 resident, prefetch its ks=0 frags
#pragma unroll
    for (int p = 0; p < STAGES - 1; ++p) {
        load_chunk(p);
        CP_COMMIT();
    }
    CP_WAIT2();
    __syncthreads();

    uint32_t afr[2][4][4], bfr[2][4][4];   // double-buffered fragments
    {
        const uint32_t ab0 = sb;
        const uint32_t bb0 = ab0 + A_BYTES;
#pragma unroll
        for (int mf = 0; mf < 4; mf++)
            LDSM4(afr[0][mf], ab0 + aRow[mf] + (akh ^ cRow));
#pragma unroll
        for (int p = 0; p < 4; p++)
            LDSM4(bfr[0][p], bb0 + bRowP[p] + (bkh ^ cRow));
    }

    const int qid = L >> 2;
    const int tc  = (L & 3) * 2;

#pragma unroll 1
    for (int ci = 0; ci < nchunks; ++ci) {
        __syncthreads();     // guard: ring-slot (ci+3)&3 refill vs its readers in ci-1

        if (ci + 3 < nchunks) load_chunk(ci + 3);
        CP_COMMIT();         // uniform group count (empty near tail)
        CP_WAIT2();          // chunks ci and ci+1 resident

        const uint32_t ab  = sb + (ci & 3) * STAGE_BYTES;
        const uint32_t bb  = ab + A_BYTES;
        const uint32_t abn = sb + ((ci + 1) & 3) * STAGE_BYTES;
        const uint32_t bbn = abn + A_BYTES;

#pragma unroll
        for (int ks = 0; ks < 4; ks++) {
            const int cur = ks & 1, nxt = cur ^ 1;
            if (ks < 3) {
                const int kb = (ks + 1) * 32;          // k16 bf16 = 32 bytes
#pragma unroll
                for (int mf = 0; mf < 4; mf++)
                    LDSM4(afr[nxt][mf], ab + aRow[mf] + ((kb + akh) ^ cRow));
#pragma unroll
                for (int p = 0; p < 4; p++)
                    LDSM4(bfr[nxt][p], bb + bRowP[p] + ((kb + bkh) ^ cRow));
            } else if (ci + 1 < nchunks) {
                // cross-chunk prefetch (works across tile boundaries: fragment
                // addresses depend only on ring slot, not on the tile)
#pragma unroll
                for (int mf = 0; mf < 4; mf++)
                    LDSM4(afr[nxt][mf], abn + aRow[mf] + (akh ^ cRow));
#pragma unroll
                for (int p = 0; p < 4; p++)
                    LDSM4(bfr[nxt][p], bbn + bRowP[p] + (bkh ^ cRow));
            }
#pragma unroll
            for (int mf = 0; mf < 4; mf++)
#pragma unroll
                for (int p = 0; p < 4; p++) {
                    HMMA(acc[mf][2 * p],     afr[cur][mf], bfr[cur][p][0], bfr[cur][p][1]);
                    HMMA(acc[mf][2 * p + 1], afr[cur][mf], bfr[cur][p][2], bfr[cur][p][3]);
                }
        }

        if ((ci & (KCH - 1)) == KCH - 1) {
            // tile finished: dequant + bias epilogue (direct global reads for
            // scales/bias — L2-resident, shared across CTAs), then reset acc.
            const int t  = cta + (ci >> 6) * NSM;
            const int bm = t >> 4;
            const int bn = t & 15;
            const float* swg = g_sw + bn * BN;
            const float* bg  = bias + bn * BN;
#pragma unroll
            for (int mf = 0; mf < 4; mf++) {
                const size_t gr0 = (size_t)bm * BM + wm * 64 + mf * 16 + qid;
                const float sx0 = g_sx[gr0];
                const float sx1 = g_sx[gr0 + 8];
                float* o0 = out + gr0 * DOUT + bn * BN;
                float* o1 = o0 + (size_t)8 * DOUT;
#pragma unroll
                for (int nf = 0; nf < 8; nf++) {
                    const int col = wn * 64 + nf * 8 + tc;
                    const float2 w2 = *reinterpret_cast<const float2*>(swg + col);
                    const float2 b2 = *reinterpret_cast<const float2*>(bg + col);
                    float2 v0, v1;
                    v0.x = acc[mf][nf][0] * (sx0 * w2.x) + b2.x;
                    v0.y = acc[mf][nf][1] * (sx0 * w2.y) + b2.y;
                    v1.x = acc[mf][nf][2] * (sx1 * w2.x) + b2.x;
                    v1.y = acc[mf][nf][3] * (sx1 * w2.y) + b2.y;
                    *reinterpret_cast<float2*>(o0 + col) = v0;
                    *reinterpret_cast<float2*>(o1 + col) = v1;
                    acc[mf][nf][0] = 0.f; acc[mf][nf][1] = 0.f;
                    acc[mf][nf][2] = 0.f; acc[mf][nf][3] = 0.f;
                }
            }
        }
    }
}

// ---------------- launch ----------------
extern "C" void kernel_launch(void* const* d_in, const int* in_sizes, int n_in,
                              void* d_out, int out_size) {
    const float* x    = (const float*)d_in[0];
    const float* W    = (const float*)d_in[1];
    const float* bias = (const float*)d_in[2];
    float* out        = (float*)d_out;

    quant_kernel<<<TOKENS + DOUT, 256>>>(x, W);

    cudaFuncSetAttribute(gemm_kernel, cudaFuncAttributeMaxDynamicSharedMemorySize, SMEM_TOTAL);
    gemm_kernel<<<NSM, 256, SMEM_TOTAL>>>(bias, out);
}

// round 13
// speedup vs baseline: 1.5027x; 1.5027x over previous
#include <cuda_runtime.h>
#include <cuda_bf16.h>
#include <cstdint>

// Problem shapes (fixed for this dataset)
#define TOKENS 8192
#define DIN    4096
#define DOUT   4096

// GEMM tiling (bf16 HMMA path, baseline PTX only: cp.async + ldmatrix + mma.sync)
#define BM 128
#define BN 256
#define BK 64                        // 64 bf16 = one 128B SW128 row
#define STAGES 4
#define KCH (DIN / BK)               // 64 k-chunks per tile
#define NTILES ((TOKENS / BM) * (DOUT / BN))   // 1024
#define NSM 148

#define A_BYTES (BM * 128)           // 16384
#define B_BYTES (BN * 128)           // 32768
#define STAGE_BYTES (A_BYTES + B_BYTES)  // 49152
#define SMEM_TOTAL (STAGES * STAGE_BYTES)  // 196608

// ---------------- device-global scratch (no allocation allowed) ----------------
__device__ __align__(256) __nv_bfloat16 g_qx[(size_t)TOKENS * DIN];
__device__ __align__(256) __nv_bfloat16 g_qw[(size_t)DOUT * DIN];
__device__ float g_sx[TOKENS];
__device__ float g_sw[DOUT];

// ---------------- PTX helpers (all baseline, compile under compute_103) --------
__device__ __forceinline__ uint32_t smem_u32(const void* p) {
    uint32_t a;
    asm("{ .reg .u64 t; cvta.to.shared.u64 t, %1; cvt.u32.u64 %0, t; }" : "=r"(a) : "l"(p));
    return a;
}

#define CP16(dst, src) \
    asm volatile("cp.async.cg.shared.global [%0], [%1], 16;\n" \
                 :: "r"(dst), "l"(__cvta_generic_to_global(src)))
#define CP_COMMIT() asm volatile("cp.async.commit_group;\n" ::: "memory")
#define CP_WAIT2()  asm volatile("cp.async.wait_group 2;\n" ::: "memory")

#define LDSM4(r, addr) \
    asm volatile("ldmatrix.sync.aligned.m8n8.x4.shared.b16 {%0,%1,%2,%3}, [%4];" \
                 : "=r"((r)[0]), "=r"((r)[1]), "=r"((r)[2]), "=r"((r)[3]) : "r"(addr))

// bf16 x bf16 -> f32 accumulate (HMMA hardware fallback path on sm_103)
#define HMMA(d, a, b0, b1) \
    asm volatile("mma.sync.aligned.m16n8k16.row.col.f32.bf16.bf16.f32 " \
                 "{%0,%1,%2,%3}, {%4,%5,%6,%7}, {%8,%9}, {%0,%1,%2,%3};" \
                 : "+f"((d)[0]), "+f"((d)[1]), "+f"((d)[2]), "+f"((d)[3]) \
                 : "r"((a)[0]), "r"((a)[1]), "r"((a)[2]), "r"((a)[3]), \
                   "r"(b0), "r"(b1))

// ---------------- quantize (fused x + W): per-row absmax -> bf16 ints + scale --
// grid = TOKENS + DOUT; 256 threads/row; thread t owns 16 consecutive floats.
__global__ void __launch_bounds__(256) quant_kernel(const float* __restrict__ x,
                                                    const float* __restrict__ W) {
    const int blk = blockIdx.x;
    const bool isW = (blk >= TOKENS);
    const int row = isW ? (blk - TOKENS) : blk;
    const float* in = isW ? W : x;
    const int tid = threadIdx.x;
    const float4* inr = reinterpret_cast<const float4*>(in + (size_t)row * DIN) + tid * 4;

    float4 v[4];
    float amax = 0.f;
#pragma unroll
    for (int i = 0; i < 4; i++) {
        v[i] = inr[i];
        amax = fmaxf(amax, fmaxf(fmaxf(fabsf(v[i].x), fabsf(v[i].y)),
                                 fmaxf(fabsf(v[i].z), fabsf(v[i].w))));
    }
#pragma unroll
    for (int o = 16; o; o >>= 1) amax = fmaxf(amax, __shfl_xor_sync(0xffffffffu, amax, o));

    __shared__ float red[8];
    __shared__ float s_bcast;
    if ((tid & 31) == 0) red[tid >> 5] = amax;
    __syncthreads();
    if (tid < 8) {
        float a = red[tid];
#pragma unroll
        for (int o = 4; o; o >>= 1) a = fmaxf(a, __shfl_xor_sync(0xffu, a, o));
        // IEEE ops to bit-match jnp: max(absmax,1e-8)/127
        if (tid == 0) s_bcast = __fdiv_rn(fmaxf(a, 1e-8f), 127.0f);
    }
    __syncthreads();
    const float s = s_bcast;

    __nv_bfloat16* q = isW ? g_qw : g_qx;
    float* sc = isW ? g_sw : g_sx;
    if (tid == 0) sc[row] = s;

    // quantized values are integers in [-127,127]: exact in bf16
    __nv_bfloat162* qp = reinterpret_cast<__nv_bfloat162*>(q + (size_t)row * DIN);
#pragma unroll
    for (int i = 0; i < 4; i++) {
        float4 t = v[i];
        // __fdiv_rn + rintf (round-half-even) matches jnp.round(a/scale) exactly
        float q0 = fminf(fmaxf(rintf(__fdiv_rn(t.x, s)), -127.f), 127.f);
        float q1 = fminf(fmaxf(rintf(__fdiv_rn(t.y, s)), -127.f), 127.f);
        float q2 = fminf(fmaxf(rintf(__fdiv_rn(t.z, s)), -127.f), 127.f);
        float q3 = fminf(fmaxf(rintf(__fdiv_rn(t.w, s)), -127.f), 127.f);
        const int p = tid * 8 + i * 2;
        qp[p]     = __floats2bfloat162_rn(q0, q1);
        qp[p + 1] = __floats2bfloat162_rn(q2, q3);
    }
}

// ---------------- GEMM: out[t,o] = (qx . qw) * sx[t]*sw[o] + bias[o] -----------
// PERSISTENT (grid=148), outer tile loop + R9-clean inner loop:
//  - per-thread address bases collapse to two registers (thrOff, smThr);
//    per-chunk math is adds only
//  - cur/next tile bases computed once per tile; loader streams the 4-stage
//    ring straight across tile boundaries (next tile chunks 0-2 in flight
//    during this tile's last iterations)
//  - epilogue OUTSIDE the inner loop (register allocation matches R9);
//    fragments re-prefetched from slot 0 afterwards (resident by wait ledger)
// 8 warps as 2(m) x 4(n); warp tile 64x64; mma m16n8k16 bf16 -> f32.
__global__ void __launch_bounds__(256, 1)
gemm_kernel(const float* __restrict__ bias, float* __restrict__ out) {
    extern __shared__ char smem[];
    const uint32_t sb = smem_u32(smem);
    const int tid = threadIdx.x;
    const int wid = tid >> 5;
    const int L   = tid & 31;
    const int cta = blockIdx.x;

    const int ntiles = (NTILES - cta + NSM - 1) / NSM;   // 6 or 7

    // collapsed per-thread load offsets:
    //  global: row=(tid>>3)+32i, col byte = (tid&7)*16  ->  thrOff + i*32*DIN elems
    //  smem:   row*128 + ((tid&7)*16 ^ ((row&7)*16))    ->  smThr + i*4096
    const size_t   thrOff = (size_t)(tid >> 3) * DIN + (size_t)(tid & 7) * 8;
    const uint32_t smThr  = (uint32_t)((tid >> 3) * 128 +
                             (((tid & 7) * 16) ^ (((tid >> 3) & 7) * 16)));

    const __nv_bfloat16 *curA, *curB, *nextA, *nextB;
    {
        const int ti = cta;
        curA = g_qx + (size_t)(ti >> 4) * BM * DIN;
        curB = g_qw + (size_t)(ti & 15) * BN * DIN;
        nextA = curA; nextB = curB;   // set properly in the tile loop
    }

    // fill ring slot (jf&3) with chunk jf (jf in 0..66; >=64 -> next tile)
    auto load_chunk = [&](int jf) {
        const __nv_bfloat16* bA = (jf < KCH) ? curA : nextA;
        const __nv_bfloat16* bB = (jf < KCH) ? curB : nextB;
        const int kt = jf & (KCH - 1);
        const __nv_bfloat16* sA = bA + kt * BK + thrOff;
        const __nv_bfloat16* sB = bB + kt * BK + thrOff;
        const uint32_t ab = sb + (jf & 3) * STAGE_BYTES + smThr;
        const uint32_t bb = ab + A_BYTES;
#pragma unroll
        for (int i = 0; i < 4; i++)
            CP16(ab + i * 4096, sA + (size_t)i * 32 * DIN);
#pragma unroll
        for (int i = 0; i < 8; i++)
            CP16(bb + i * 4096, sB + (size_t)i * 32 * DIN);
    };

    // warp layout + per-lane ldmatrix address constants
    const int wm = wid >> 2;             // 0..1 -> 64 M rows
    const int wn = wid & 3;              // 0..3 -> 64 N cols
    const int lr = L & 7;
    const int cRow = lr * 16;            // swizzle XOR term ((row&7)*16)
    const int akh = ((L >> 4) & 1) * 16; // A k-half select (matrices 2,3)
    const int bkh = ((L >> 3) & 1) * 16; // B k-half select (matrices 1,3)

    uint32_t aRow[4], bRowP[4];
#pragma unroll
    for (int mf = 0; mf < 4; mf++)
        aRow[mf] = (uint32_t)(wm * 64 + mf * 16 + lr + ((L >> 3) & 1) * 8) * 128;
    // B x4 pairing: lanes 0-15 -> n8 block 2p (k lo/hi), lanes 16-31 -> block 2p+1
#pragma unroll
    for (int p = 0; p < 4; p++)
        bRowP[p] = (uint32_t)(wn * 64 + p * 16 + ((L >> 4) & 1) * 8 + lr) * 128;

    float acc[4][8][4];
#pragma unroll
    for (int mf = 0; mf < 4; mf++)
#pragma unroll
        for (int nf = 0; nf < 8; nf++)
#pragma unroll
            for (int j = 0; j < 4; j++) acc[mf][nf][j] = 0.f;

    // prologue: chunks 0..2 of first tile; prefetch ks=0 fragments from slot 0
#pragma unroll
    for (int p = 0; p < STAGES - 1; ++p) {
        load_chunk(p);
        CP_COMMIT();
    }
    CP_WAIT2();
    __syncthreads();

    uint32_t afr[2][4][4], bfr[2][4][4];   // double-buffered fragments
    {
        const uint32_t bb0 = sb + A_BYTES;
#pragma unroll
        for (int mf = 0; mf < 4; mf++)
            LDSM4(afr[0][mf], sb + aRow[mf] + (akh ^ cRow));
#pragma unroll
        for (int p = 0; p < 4; p++)
            LDSM4(bfr[0][p], bb0 + bRowP[p] + (bkh ^ cRow));
    }

    const int qid = L >> 2;
    const int tc  = (L & 3) * 2;

    int ti = cta;
#pragma unroll 1
    for (int w = 0; w < ntiles; ++w) {
        const int tiN = ti + NSM;
        if (tiN < NTILES) {
            nextA = g_qx + (size_t)(tiN >> 4) * BM * DIN;
            nextB = g_qw + (size_t)(tiN & 15) * BN * DIN;
        } else {
            nextA = curA; nextB = curB;   // harmless refill on final tile
        }

#pragma unroll 1
        for (int it = 0; it < KCH; ++it) {
            __syncthreads();     // guard: ring-slot (it+3)&3 refill vs readers in it-1

            load_chunk(it + 3);  // streams into next tile for it >= 61
            CP_COMMIT();
            CP_WAIT2();          // chunks it and it+1 resident

            const uint32_t ab  = sb + (it & 3) * STAGE_BYTES;
            const uint32_t bb  = ab + A_BYTES;
            const uint32_t abn = sb + ((it + 1) & 3) * STAGE_BYTES;
            const uint32_t bbn = abn + A_BYTES;

#pragma unroll
            for (int ks = 0; ks < 4; ks++) {
                const int cur = ks & 1, nxt = cur ^ 1;
                if (ks < 3) {
                    const int kb = (ks + 1) * 32;          // k16 bf16 = 32 bytes
#pragma unroll
                    for (int mf = 0; mf < 4; mf++)
                        LDSM4(afr[nxt][mf], ab + aRow[mf] + ((kb + akh) ^ cRow));
#pragma unroll
                    for (int p = 0; p < 4; p++)
                        LDSM4(bfr[nxt][p], bb + bRowP[p] + ((kb + bkh) ^ cRow));
                } else if (it + 1 < KCH) {
                    // cross-chunk prefetch within the tile
#pragma unroll
                    for (int mf = 0; mf < 4; mf++)
                        LDSM4(afr[nxt][mf], abn + aRow[mf] + (akh ^ cRow));
#pragma unroll
                    for (int p = 0; p < 4; p++)
                        LDSM4(bfr[nxt][p], bbn + bRowP[p] + (bkh ^ cRow));
                }
#pragma unroll
                for (int mf = 0; mf < 4; mf++)
#pragma unroll
                    for (int p = 0; p < 4; p++) {
                        HMMA(acc[mf][2 * p],     afr[cur][mf], bfr[cur][p][0], bfr[cur][p][1]);
                        HMMA(acc[mf][2 * p + 1], afr[cur][mf], bfr[cur][p][2], bfr[cur][p][3]);
                    }
            }
        }

        // tile epilogue: dequant + bias (scales/bias L2-resident), reset acc
        {
            const int bm = ti >> 4;
            const int bn = ti & 15;
            const float* swg = g_sw + bn * BN;
            const float* bg  = bias + bn * BN;
#pragma unroll
            for (int mf = 0; mf < 4; mf++) {
                const size_t gr0 = (size_t)bm * BM + wm * 64 + mf * 16 + qid;
                const float sx0 = g_sx[gr0];
                const float sx1 = g_sx[gr0 + 8];
                float* o0 = out + gr0 * DOUT + bn * BN;
                float* o1 = o0 + (size_t)8 * DOUT;
#pragma unroll
                for (int nf = 0; nf < 8; nf++) {
                    const int col = wn * 64 + nf * 8 + tc;
                    const float2 w2 = *reinterpret_cast<const float2*>(swg + col);
                    const float2 b2 = *reinterpret_cast<const float2*>(bg + col);
                    float2 v0, v1;
                    v0.x = acc[mf][nf][0] * (sx0 * w2.x) + b2.x;
                    v0.y = acc[mf][nf][1] * (sx0 * w2.y) + b2.y;
                    v1.x = acc[mf][nf][2] * (sx1 * w2.x) + b2.x;
                    v1.y = acc[mf][nf][3] * (sx1 * w2.y) + b2.y;
                    *reinterpret_cast<float2*>(o0 + col) = v0;
                    *reinterpret_cast<float2*>(o1 + col) = v1;
                    acc[mf][nf][0] = 0.f; acc[mf][nf][1] = 0.f;
                    acc[mf][nf][2] = 0.f; acc[mf][nf][3] = 0.f;
                }
            }
        }

        // advance to next tile; re-prefetch its ks=0 fragments from slot 0
        ti = tiN; curA = nextA; curB = nextB;
        if (w + 1 < ntiles) {
            const uint32_t bb0 = sb + A_BYTES;
#pragma unroll
            for (int mf = 0; mf < 4; mf++)
                LDSM4(afr[0][mf], sb + aRow[mf] + (akh ^ cRow));
#pragma unroll
            for (int p = 0; p < 4; p++)
                LDSM4(bfr[0][p], bb0 + bRowP[p] + (bkh ^ cRow));
        }
    }
}

// ---------------- launch ----------------
extern "C" void kernel_launch(void* const* d_in, const int* in_sizes, int n_in,
                              void* d_out, int out_size) {
    const float* x    = (const float*)d_in[0];
    const float* W    = (const float*)d_in[1];
    const float* bias = (const float*)d_in[2];
    float* out        = (float*)d_out;

    quant_kernel<<<TOKENS + DOUT, 256>>>(x, W);

    cudaFuncSetAttribute(gemm_kernel, cudaFuncAttributeMaxDynamicSharedMemorySize, SMEM_TOTAL);
    gemm_kernel<<<NSM, 256, SMEM_TOTAL>>>(bias, out);
}

// round 14
// speedup vs baseline: 1.5451x; 1.0282x over previous
#include <cuda_runtime.h>
#include <cuda_bf16.h>
#include <cstdint>

// Problem shapes (fixed for this dataset)
#define TOKENS 8192
#define DIN    4096
#define DOUT   4096

// GEMM tiling (bf16 HMMA path, baseline PTX only: cp.async + ldmatrix + mma.sync)
#define BM 128
#define BN 256
#define BK 64                        // 64 bf16 = one 128B SW128 row
#define STAGES 4
#define KCH (DIN / BK)               // 64 k-chunks per tile
#define NTILES ((TOKENS / BM) * (DOUT / BN))   // 1024
#define NSM 148

#define A_BYTES (BM * 128)           // 16384
#define B_BYTES (BN * 128)           // 32768
#define STAGE_BYTES (A_BYTES + B_BYTES)  // 49152
#define SMEM_TOTAL (STAGES * STAGE_BYTES)  // 196608

// ---------------- device-global scratch (no allocation allowed) ----------------
__device__ __align__(256) __nv_bfloat16 g_qx[(size_t)TOKENS * DIN];
__device__ __align__(256) __nv_bfloat16 g_qw[(size_t)DOUT * DIN];
__device__ float g_sx[TOKENS];
__device__ float g_sw[DOUT];

// ---------------- PTX helpers (all baseline, compile under compute_103) --------
__device__ __forceinline__ uint32_t smem_u32(const void* p) {
    uint32_t a;
    asm("{ .reg .u64 t; cvta.to.shared.u64 t, %1; cvt.u32.u64 %0, t; }" : "=r"(a) : "l"(p));
    return a;
}

#define CP16(dst, src) \
    asm volatile("cp.async.cg.shared.global [%0], [%1], 16;\n" \
                 :: "r"(dst), "l"(__cvta_generic_to_global(src)))
#define CP_COMMIT() asm volatile("cp.async.commit_group;\n" ::: "memory")
#define CP_WAIT2()  asm volatile("cp.async.wait_group 2;\n" ::: "memory")

#define LDSM4(r, addr) \
    asm volatile("ldmatrix.sync.aligned.m8n8.x4.shared.b16 {%0,%1,%2,%3}, [%4];" \
                 : "=r"((r)[0]), "=r"((r)[1]), "=r"((r)[2]), "=r"((r)[3]) : "r"(addr))

// bf16 x bf16 -> f32 accumulate (HMMA hardware fallback path on sm_103)
#define HMMA(d, a, b0, b1) \
    asm volatile("mma.sync.aligned.m16n8k16.row.col.f32.bf16.bf16.f32 " \
                 "{%0,%1,%2,%3}, {%4,%5,%6,%7}, {%8,%9}, {%0,%1,%2,%3};" \
                 : "+f"((d)[0]), "+f"((d)[1]), "+f"((d)[2]), "+f"((d)[3]) \
                 : "r"((a)[0]), "r"((a)[1]), "r"((a)[2]), "r"((a)[3]), \
                   "r"(b0), "r"(b1))

// ---------------- quantize (fused x + W): per-row absmax -> bf16 ints + scale --
// grid = TOKENS + DOUT; 256 threads/row; thread t owns 16 consecutive floats.
__global__ void __launch_bounds__(256) quant_kernel(const float* __restrict__ x,
                                                    const float* __restrict__ W) {
    const int blk = blockIdx.x;
    const bool isW = (blk >= TOKENS);
    const int row = isW ? (blk - TOKENS) : blk;
    const float* in = isW ? W : x;
    const int tid = threadIdx.x;
    const float4* inr = reinterpret_cast<const float4*>(in + (size_t)row * DIN) + tid * 4;

    float4 v[4];
    float amax = 0.f;
#pragma unroll
    for (int i = 0; i < 4; i++) {
        v[i] = inr[i];
        amax = fmaxf(amax, fmaxf(fmaxf(fabsf(v[i].x), fabsf(v[i].y)),
                                 fmaxf(fabsf(v[i].z), fabsf(v[i].w))));
    }
#pragma unroll
    for (int o = 16; o; o >>= 1) amax = fmaxf(amax, __shfl_xor_sync(0xffffffffu, amax, o));

    __shared__ float red[8];
    __shared__ float s_bcast;
    if ((tid & 31) == 0) red[tid >> 5] = amax;
    __syncthreads();
    if (tid < 8) {
        float a = red[tid];
#pragma unroll
        for (int o = 4; o; o >>= 1) a = fmaxf(a, __shfl_xor_sync(0xffu, a, o));
        // IEEE ops to bit-match jnp: max(absmax,1e-8)/127
        if (tid == 0) s_bcast = __fdiv_rn(fmaxf(a, 1e-8f), 127.0f);
    }
    __syncthreads();
    const float s = s_bcast;

    __nv_bfloat16* q = isW ? g_qw : g_qx;
    float* sc = isW ? g_sw : g_sx;
    if (tid == 0) sc[row] = s;

    // quantized values are integers in [-127,127]: exact in bf16
    __nv_bfloat162* qp = reinterpret_cast<__nv_bfloat162*>(q + (size_t)row * DIN);
#pragma unroll
    for (int i = 0; i < 4; i++) {
        float4 t = v[i];
        // __fdiv_rn + rintf (round-half-even) matches jnp.round(a/scale) exactly
        float q0 = fminf(fmaxf(rintf(__fdiv_rn(t.x, s)), -127.f), 127.f);
        float q1 = fminf(fmaxf(rintf(__fdiv_rn(t.y, s)), -127.f), 127.f);
        float q2 = fminf(fmaxf(rintf(__fdiv_rn(t.z, s)), -127.f), 127.f);
        float q3 = fminf(fmaxf(rintf(__fdiv_rn(t.w, s)), -127.f), 127.f);
        const int p = tid * 8 + i * 2;
        qp[p]     = __floats2bfloat162_rn(q0, q1);
        qp[p + 1] = __floats2bfloat162_rn(q2, q3);
    }
}

// ---------------- GEMM: out[t,o] = (qx . qw) * sx[t]*sw[o] + bias[o] -----------
// PERSISTENT (grid=148). vs R12: the per-chunk 12x cp.async burst is spread
// through the ks loop (4 at ks=0/1/2, between LDSM prefetch and HMMAs) so the
// tensor pipe starts immediately after the head barrier; commit + wait_group 2
// moved to ks=3, exactly where the cross-chunk fragment prefetch needs chunk
// it+1 resident (ledger: after committing it+3, <=2 pending => it+1 done).
// Chunk `it` itself is resident from the PREVIOUS iteration's wait.
// 8 warps as 2(m) x 4(n); warp tile 64x64; mma m16n8k16 bf16 -> f32.
__global__ void __launch_bounds__(256, 1)
gemm_kernel(const float* __restrict__ bias, float* __restrict__ out) {
    extern __shared__ char smem[];
    const uint32_t sb = smem_u32(smem);
    const int tid = threadIdx.x;
    const int wid = tid >> 5;
    const int L   = tid & 31;
    const int cta = blockIdx.x;

    const int ntiles = (NTILES - cta + NSM - 1) / NSM;   // 6 or 7

    // collapsed per-thread load offsets:
    //  global: row=(tid>>3)+32i, col byte = (tid&7)*16  ->  thrOff + i*32*DIN elems
    //  smem:   row*128 + ((tid&7)*16 ^ ((row&7)*16))    ->  smThr + i*4096
    const size_t   thrOff = (size_t)(tid >> 3) * DIN + (size_t)(tid & 7) * 8;
    const uint32_t smThr  = (uint32_t)((tid >> 3) * 128 +
                             (((tid & 7) * 16) ^ (((tid >> 3) & 7) * 16)));

    const __nv_bfloat16 *curA, *curB, *nextA, *nextB;
    curA = g_qx + (size_t)(cta >> 4) * BM * DIN;
    curB = g_qw + (size_t)(cta & 15) * BN * DIN;
    nextA = curA; nextB = curB;

    // full-chunk loader (prologue only)
    auto load_chunk = [&](int jf) {
        const __nv_bfloat16* sA = curA + jf * BK + thrOff;
        const __nv_bfloat16* sB = curB + jf * BK + thrOff;
        const uint32_t ab = sb + (jf & 3) * STAGE_BYTES + smThr;
        const uint32_t bb = ab + A_BYTES;
#pragma unroll
        for (int i = 0; i < 4; i++)
            CP16(ab + i * 4096, sA + (size_t)i * 32 * DIN);
#pragma unroll
        for (int i = 0; i < 8; i++)
            CP16(bb + i * 4096, sB + (size_t)i * 32 * DIN);
    };

    // warp layout + per-lane ldmatrix address constants
    const int wm = wid >> 2;             // 0..1 -> 64 M rows
    const int wn = wid & 3;              // 0..3 -> 64 N cols
    const int lr = L & 7;
    const int cRow = lr * 16;            // swizzle XOR term ((row&7)*16)
    const int akh = ((L >> 4) & 1) * 16; // A k-half select (matrices 2,3)
    const int bkh = ((L >> 3) & 1) * 16; // B k-half select (matrices 1,3)

    uint32_t aRow[4], bRowP[4];
#pragma unroll
    for (int mf = 0; mf < 4; mf++)
        aRow[mf] = (uint32_t)(wm * 64 + mf * 16 + lr + ((L >> 3) & 1) * 8) * 128;
    // B x4 pairing: lanes 0-15 -> n8 block 2p (k lo/hi), lanes 16-31 -> block 2p+1
#pragma unroll
    for (int p = 0; p < 4; p++)
        bRowP[p] = (uint32_t)(wn * 64 + p * 16 + ((L >> 4) & 1) * 8 + lr) * 128;

    float acc[4][8][4];
#pragma unroll
    for (int mf = 0; mf < 4; mf++)
#pragma unroll
        for (int nf = 0; nf < 8; nf++)
#pragma unroll
            for (int j = 0; j < 4; j++) acc[mf][nf][j] = 0.f;

    // prologue: chunks 0..2 of first tile; prefetch ks=0 fragments from slot 0
#pragma unroll
    for (int p = 0; p < STAGES - 1; ++p) {
        load_chunk(p);
        CP_COMMIT();
    }
    CP_WAIT2();
    __syncthreads();

    uint32_t afr[2][4][4], bfr[2][4][4];   // double-buffered fragments
    {
        const uint32_t bb0 = sb + A_BYTES;
#pragma unroll
        for (int mf = 0; mf < 4; mf++)
            LDSM4(afr[0][mf], sb + aRow[mf] + (akh ^ cRow));
#pragma unroll
        for (int p = 0; p < 4; p++)
            LDSM4(bfr[0][p], bb0 + bRowP[p] + (bkh ^ cRow));
    }

    const int qid = L >> 2;
    const int tc  = (L & 3) * 2;

    int ti = cta;
#pragma unroll 1
    for (int w = 0; w < ntiles; ++w) {
        const int tiN = ti + NSM;
        if (tiN < NTILES) {
            nextA = g_qx + (size_t)(tiN >> 4) * BM * DIN;
            nextB = g_qw + (size_t)(tiN & 15) * BN * DIN;
        } else {
            nextA = curA; nextB = curB;   // harmless refill on final tile
        }

#pragma unroll 1
        for (int it = 0; it < KCH; ++it) {
            __syncthreads();     // guard: ring-slot (it+3)&3 refill vs readers in it-1

            // per-iteration fill sources for chunk it+3 (>=64 -> next tile)
            const int jf = it + 3;
            const __nv_bfloat16* sA = ((jf < KCH) ? curA : nextA)
                                      + (jf & (KCH - 1)) * BK + thrOff;
            const __nv_bfloat16* sB = ((jf < KCH) ? curB : nextB)
                                      + (jf & (KCH - 1)) * BK + thrOff;
            const uint32_t ab3 = sb + (jf & 3) * STAGE_BYTES + smThr;
            const uint32_t bb3 = ab3 + A_BYTES;

            const uint32_t ab  = sb + (it & 3) * STAGE_BYTES;
            const uint32_t bb  = ab + A_BYTES;
            const uint32_t abn = sb + ((it + 1) & 3) * STAGE_BYTES;
            const uint32_t bbn = abn + A_BYTES;

#pragma unroll
            for (int ks = 0; ks < 4; ks++) {
                const int cur = ks & 1, nxt = cur ^ 1;
                if (ks < 3) {
                    const int kb = (ks + 1) * 32;          // k16 bf16 = 32 bytes
#pragma unroll
                    for (int mf = 0; mf < 4; mf++)
                        LDSM4(afr[nxt][mf], ab + aRow[mf] + ((kb + akh) ^ cRow));
#pragma unroll
                    for (int p = 0; p < 4; p++)
                        LDSM4(bfr[nxt][p], bb + bRowP[p] + ((kb + bkh) ^ cRow));
                    // distribute the chunk-fill burst: 4 cp.async per ks
                    if (ks == 0) {
#pragma unroll
                        for (int i = 0; i < 4; i++)
                            CP16(ab3 + i * 4096, sA + (size_t)i * 32 * DIN);
                    } else if (ks == 1) {
#pragma unroll
                        for (int i = 0; i < 4; i++)
                            CP16(bb3 + i * 4096, sB + (size_t)i * 32 * DIN);
                    } else {
#pragma unroll
                        for (int i = 4; i < 8; i++)
                            CP16(bb3 + i * 4096, sB + (size_t)i * 32 * DIN);
                    }
                } else {
                    CP_COMMIT();     // chunk it+3 group (uniform cadence)
                    CP_WAIT2();      // <=2 pending -> chunk it+1 resident
                    if (it + 1 < KCH) {
                        // cross-chunk prefetch of (it+1, ks=0)
#pragma unroll
                        for (int mf = 0; mf < 4; mf++)
                            LDSM4(afr[nxt][mf], abn + aRow[mf] + (akh ^ cRow));
#pragma unroll
                        for (int p = 0; p < 4; p++)
                            LDSM4(bfr[nxt][p], bbn + bRowP[p] + (bkh ^ cRow));
                    }
                }
#pragma unroll
                for (int mf = 0; mf < 4; mf++)
#pragma unroll
                    for (int p = 0; p < 4; p++) {
                        HMMA(acc[mf][2 * p],     afr[cur][mf], bfr[cur][p][0], bfr[cur][p][1]);
                        HMMA(acc[mf][2 * p + 1], afr[cur][mf], bfr[cur][p][2], bfr[cur][p][3]);
                    }
            }
        }

        // tile epilogue: dequant + bias (scales/bias L2-resident), reset acc
        {
            const int bm = ti >> 4;
            const int bn = ti & 15;
            const float* swg = g_sw + bn * BN;
            const float* bg  = bias + bn * BN;
#pragma unroll
            for (int mf = 0; mf < 4; mf++) {
                const size_t gr0 = (size_t)bm * BM + wm * 64 + mf * 16 + qid;
                const float sx0 = g_sx[gr0];
                const float sx1 = g_sx[gr0 + 8];
                float* o0 = out + gr0 * DOUT + bn * BN;
                float* o1 = o0 + (size_t)8 * DOUT;
#pragma unroll
                for (int nf = 0; nf < 8; nf++) {
                    const int col = wn * 64 + nf * 8 + tc;
                    const float2 w2 = *reinterpret_cast<const float2*>(swg + col);
                    const float2 b2 = *reinterpret_cast<const float2*>(bg + col);
                    float2 v0, v1;
                    v0.x = acc[mf][nf][0] * (sx0 * w2.x) + b2.x;
                    v0.y = acc[mf][nf][1] * (sx0 * w2.y) + b2.y;
                    v1.x = acc[mf][nf][2] * (sx1 * w2.x) + b2.x;
                    v1.y = acc[mf][nf][3] * (sx1 * w2.y) + b2.y;
                    *reinterpret_cast<float2*>(o0 + col) = v0;
                    *reinterpret_cast<float2*>(o1 + col) = v1;
                    acc[mf][nf][0] = 0.f; acc[mf][nf][1] = 0.f;
                    acc[mf][nf][2] = 0.f; acc[mf][nf][3] = 0.f;
                }
            }
        }

        // advance to next tile; re-prefetch its ks=0 fragments from slot 0
        // (chunk 64 resident: committed at it=61, waited at it=63's ks=3)
        ti = tiN; curA = nextA; curB = nextB;
        if (w + 1 < ntiles) {
            const uint32_t bb0 = sb + A_BYTES;
#pragma unroll
            for (int mf = 0; mf < 4; mf++)
                LDSM4(afr[0][mf], sb + aRow[mf] + (akh ^ cRow));
#pragma unroll
            for (int p = 0; p < 4; p++)
                LDSM4(bfr[0][p], bb0 + bRowP[p] + (bkh ^ cRow));
        }
    }
}

// ---------------- launch ----------------
extern "C" void kernel_launch(void* const* d_in, const int* in_sizes, int n_in,
                              void* d_out, int out_size) {
    const float* x    = (const float*)d_in[0];
    const float* W    = (const float*)d_in[1];
    const float* bias = (const float*)d_in[2];
    float* out        = (float*)d_out;

    quant_kernel<<<TOKENS + DOUT, 256>>>(x, W);

    cudaFuncSetAttribute(gemm_kernel, cudaFuncAttributeMaxDynamicSharedMemorySize, SMEM_TOTAL);
    gemm_kernel<<<NSM, 256, SMEM_TOTAL>>>(bias, out);
}

// round 16
// speedup vs baseline: 1.6306x; 1.0554x over previous
#include <cuda_runtime.h>
#include <cuda_bf16.h>
#include <cstdint>

// Problem shapes (fixed for this dataset)
#define TOKENS 8192
#define DIN    4096
#define DOUT   4096

// GEMM tiling (bf16 HMMA path, baseline PTX only: cp.async + ldmatrix + mma.sync)
// 2 CTAs/SM: 128 threads, BM=128 x BN=128 tile, 4 warps as 2x2 of 64x64.
#define BM 128
#define BN 128
#define BK 64                        // 64 bf16 = one 128B SW128 row
#define STAGES 3
#define KCH (DIN / BK)               // 64 k-chunks per tile
#define NTILES ((TOKENS / BM) * (DOUT / BN))   // 2048
#define NSM 148
#define NCTA (2 * NSM)               // 296

#define A_BYTES (BM * 128)           // 16384
#define B_BYTES (BN * 128)           // 16384
#define STAGE_BYTES (A_BYTES + B_BYTES)    // 32768
#define SMEM_TOTAL (STAGES * STAGE_BYTES)  // 98304 per CTA (2 per SM = 192KB)

// ---------------- device-global scratch (no allocation allowed) ----------------
__device__ __align__(256) __nv_bfloat16 g_qx[(size_t)TOKENS * DIN];
__device__ __align__(256) __nv_bfloat16 g_qw[(size_t)DOUT * DIN];
__device__ float g_sx[TOKENS];
__device__ float g_sw[DOUT];

// ---------------- PTX helpers (all baseline, compile under compute_103) --------
__device__ __forceinline__ uint32_t smem_u32(const void* p) {
    uint32_t a;
    asm("{ .reg .u64 t; cvta.to.shared.u64 t, %1; cvt.u32.u64 %0, t; }" : "=r"(a) : "l"(p));
    return a;
}

#define CP16(dst, src) \
    asm volatile("cp.async.cg.shared.global [%0], [%1], 16;\n" \
                 :: "r"(dst), "l"(__cvta_generic_to_global(src)))
#define CP_COMMIT() asm volatile("cp.async.commit_group;\n" ::: "memory")
#define CP_WAIT1()  asm volatile("cp.async.wait_group 1;\n" ::: "memory")

#define LDSM4(r, addr) \
    asm volatile("ldmatrix.sync.aligned.m8n8.x4.shared.b16 {%0,%1,%2,%3}, [%4];" \
                 : "=r"((r)[0]), "=r"((r)[1]), "=r"((r)[2]), "=r"((r)[3]) : "r"(addr))

// bf16 x bf16 -> f32 accumulate (HMMA hardware fallback path on sm_103)
#define HMMA(d, a, b0, b1) \
    asm volatile("mma.sync.aligned.m16n8k16.row.col.f32.bf16.bf16.f32 " \
                 "{%0,%1,%2,%3}, {%4,%5,%6,%7}, {%8,%9}, {%0,%1,%2,%3};" \
                 : "+f"((d)[0]), "+f"((d)[1]), "+f"((d)[2]), "+f"((d)[3]) \
                 : "r"((a)[0]), "r"((a)[1]), "r"((a)[2]), "r"((a)[3]), \
                   "r"(b0), "r"(b1))

// ---------------- quantize (fused x + W): per-row absmax -> bf16 ints + scale --
// grid = TOKENS + DOUT; 256 threads/row; thread t owns 16 consecutive floats.
__global__ void __launch_bounds__(256) quant_kernel(const float* __restrict__ x,
                                                    const float* __restrict__ W) {
    const int blk = blockIdx.x;
    const bool isW = (blk >= TOKENS);
    const int row = isW ? (blk - TOKENS) : blk;
    const float* in = isW ? W : x;
    const int tid = threadIdx.x;
    const float4* inr = reinterpret_cast<const float4*>(in + (size_t)row * DIN) + tid * 4;

    float4 v[4];
    float amax = 0.f;
#pragma unroll
    for (int i = 0; i < 4; i++) {
        v[i] = inr[i];
        amax = fmaxf(amax, fmaxf(fmaxf(fabsf(v[i].x), fabsf(v[i].y)),
                                 fmaxf(fabsf(v[i].z), fabsf(v[i].w))));
    }
#pragma unroll
    for (int o = 16; o; o >>= 1) amax = fmaxf(amax, __shfl_xor_sync(0xffffffffu, amax, o));

    __shared__ float red[8];
    __shared__ float s_bcast;
    if ((tid & 31) == 0) red[tid >> 5] = amax;
    __syncthreads();
    if (tid < 8) {
        float a = red[tid];
#pragma unroll
        for (int o = 4; o; o >>= 1) a = fmaxf(a, __shfl_xor_sync(0xffu, a, o));
        // IEEE ops to bit-match jnp: max(absmax,1e-8)/127
        if (tid == 0) s_bcast = __fdiv_rn(fmaxf(a, 1e-8f), 127.0f);
    }
    __syncthreads();
    const float s = s_bcast;

    __nv_bfloat16* q = isW ? g_qw : g_qx;
    float* sc = isW ? g_sw : g_sx;
    if (tid == 0) sc[row] = s;

    // quantized values are integers in [-127,127]: exact in bf16
    __nv_bfloat162* qp = reinterpret_cast<__nv_bfloat162*>(q + (size_t)row * DIN);
#pragma unroll
    for (int i = 0; i < 4; i++) {
        float4 t = v[i];
        // __fdiv_rn + rintf (round-half-even) matches jnp.round(a/scale) exactly
        float q0 = fminf(fmaxf(rintf(__fdiv_rn(t.x, s)), -127.f), 127.f);
        float q1 = fminf(fmaxf(rintf(__fdiv_rn(t.y, s)), -127.f), 127.f);
        float q2 = fminf(fmaxf(rintf(__fdiv_rn(t.z, s)), -127.f), 127.f);
        float q3 = fminf(fmaxf(rintf(__fdiv_rn(t.w, s)), -127.f), 127.f);
        const int p = tid * 8 + i * 2;
        qp[p]     = __floats2bfloat162_rn(q0, q1);
        qp[p + 1] = __floats2bfloat162_rn(q2, q3);
    }
}

// ---------------- GEMM: out[t,o] = (qx . qw) * sx[t]*sw[o] + bias[o] -----------
// PERSISTENT, 2 CTAs/SM (grid=296, 128 threads).
// RACE FIX vs R14: cp.async wait_group is PER-THREAD, so any LDSM of data
// copied by OTHER threads needs wait + __syncthreads. The per-iteration
// barrier now sits at ks=3 immediately after CP_WAIT1 (before the cross-chunk
// prefetch), which ALSO subsumes the slot-reuse guard (last read of chunk it
// is at ks=2, before the barrier; its slot refills at it+1 ks=0, after it),
// so the head barrier is removed — same one barrier per iteration.
// 3-stage ring: fill chunk it+2 spread over ks=0/1/2; commit+wait+barrier at
// ks=3 => chunk it+1 visible to ALL threads for the cross-chunk prefetch.
// Slot index = global chunk counter mod 3, carried across tiles.
// 4 warps as 2(m) x 2(n); warp tile 64x64; mma m16n8k16 bf16 -> f32.
__global__ void __launch_bounds__(128, 2)
gemm_kernel(const float* __restrict__ bias, float* __restrict__ out) {
    extern __shared__ char smem[];
    const uint32_t sb = smem_u32(smem);
    const int tid = threadIdx.x;
    const int wid = tid >> 5;
    const int L   = tid & 31;
    const int cta = blockIdx.x;

    const int ntiles = (NTILES - cta + NCTA - 1) / NCTA;   // 6 or 7

    // collapsed per-thread load offsets (128 threads, 16 rows per pass):
    //  global: row=(tid>>3)+16i, col byte=(tid&7)*16 -> thrOff + i*16*DIN elems
    //  smem:   row*128 + ((tid&7)*16 ^ ((row&7)*16)) -> smThr + i*2048
    const size_t   thrOff = (size_t)(tid >> 3) * DIN + (size_t)(tid & 7) * 8;
    const uint32_t smThr  = (uint32_t)((tid >> 3) * 128 +
                             (((tid & 7) * 16) ^ (((tid >> 3) & 7) * 16)));

    const __nv_bfloat16 *curA, *curB, *nextA, *nextB;
    curA = g_qx + (size_t)(cta >> 5) * BM * DIN;      // bm = ti>>5
    curB = g_qw + (size_t)(cta & 31) * BN * DIN;      // bn = ti&31
    nextA = curA; nextB = curB;

    // full-chunk loader (prologue only); slot passed explicitly
    auto load_chunk = [&](int kt, int slot) {
        const __nv_bfloat16* sA = curA + kt * BK + thrOff;
        const __nv_bfloat16* sB = curB + kt * BK + thrOff;
        const uint32_t ab = sb + slot * STAGE_BYTES + smThr;
        const uint32_t bb = ab + A_BYTES;
#pragma unroll
        for (int i = 0; i < 8; i++)
            CP16(ab + i * 2048, sA + (size_t)i * 16 * DIN);
#pragma unroll
        for (int i = 0; i < 8; i++)
            CP16(bb + i * 2048, sB + (size_t)i * 16 * DIN);
    };

    // warp layout + per-lane ldmatrix address constants
    const int wm = wid >> 1;             // 0..1 -> 64 M rows
    const int wn = wid & 1;              // 0..1 -> 64 N cols
    const int lr = L & 7;
    const int cRow = lr * 16;            // swizzle XOR term ((row&7)*16)
    const int akh = ((L >> 4) & 1) * 16; // A k-half select (matrices 2,3)
    const int bkh = ((L >> 3) & 1) * 16; // B k-half select (matrices 1,3)

    uint32_t aRow[4], bRowP[4];
#pragma unroll
    for (int mf = 0; mf < 4; mf++)
        aRow[mf] = (uint32_t)(wm * 64 + mf * 16 + lr + ((L >> 3) & 1) * 8) * 128;
    // B x4 pairing: lanes 0-15 -> n8 block 2p (k lo/hi), lanes 16-31 -> block 2p+1
#pragma unroll
    for (int p = 0; p < 4; p++)
        bRowP[p] = (uint32_t)(wn * 64 + p * 16 + ((L >> 4) & 1) * 8 + lr) * 128;

    float acc[4][8][4];
#pragma unroll
    for (int mf = 0; mf < 4; mf++)
#pragma unroll
        for (int nf = 0; nf < 8; nf++)
#pragma unroll
            for (int j = 0; j < 4; j++) acc[mf][nf][j] = 0.f;

    // prologue: chunks 0,1 -> slots 0,1; wait + BARRIER => chunk 0 visible to all
    load_chunk(0, 0);
    CP_COMMIT();
    load_chunk(1, 1);
    CP_COMMIT();
    CP_WAIT1();
    __syncthreads();

    uint32_t afr[2][4][4], bfr[2][4][4];   // double-buffered fragments
    {
        const uint32_t bb0 = sb + A_BYTES;
#pragma unroll
        for (int mf = 0; mf < 4; mf++)
            LDSM4(afr[0][mf], sb + aRow[mf] + (akh ^ cRow));
#pragma unroll
        for (int p = 0; p < 4; p++)
            LDSM4(bfr[0][p], bb0 + bRowP[p] + (bkh ^ cRow));
    }

    const int qid = L >> 2;
    const int tc  = (L & 3) * 2;

    int ti = cta;
    int slotC = 0;                        // global-chunk slot, carried across tiles
#pragma unroll 1
    for (int w = 0; w < ntiles; ++w) {
        const int tiN = ti + NCTA;
        if (tiN < NTILES) {
            nextA = g_qx + (size_t)(tiN >> 5) * BM * DIN;
            nextB = g_qw + (size_t)(tiN & 31) * BN * DIN;
        } else {
            nextA = curA; nextB = curB;   // harmless refill on final tile
        }

#pragma unroll 1
        for (int it = 0; it < KCH; ++it) {
            int slotN = slotC + 1; if (slotN == STAGES) slotN = 0;
            int slotF = slotN + 1; if (slotF == STAGES) slotF = 0;

            // fill sources for chunk it+2 (>=64 -> next tile)
            const int jf = it + 2;
            const __nv_bfloat16* sA = ((jf < KCH) ? curA : nextA)
                                      + (jf & (KCH - 1)) * BK + thrOff;
            const __nv_bfloat16* sB = ((jf < KCH) ? curB : nextB)
                                      + (jf & (KCH - 1)) * BK + thrOff;
            const uint32_t abF = sb + slotF * STAGE_BYTES + smThr;
            const uint32_t bbF = abF + A_BYTES;

            const uint32_t ab  = sb + slotC * STAGE_BYTES;
            const uint32_t bb  = ab + A_BYTES;
            const uint32_t abn = sb + slotN * STAGE_BYTES;
            const uint32_t bbn = abn + A_BYTES;

#pragma unroll
            for (int ks = 0; ks < 4; ks++) {
                const int cur = ks & 1, nxt = cur ^ 1;
                if (ks < 3) {
                    const int kb = (ks + 1) * 32;          // k16 bf16 = 32 bytes
#pragma unroll
                    for (int mf = 0; mf < 4; mf++)
                        LDSM4(afr[nxt][mf], ab + aRow[mf] + ((kb + akh) ^ cRow));
#pragma unroll
                    for (int p = 0; p < 4; p++)
                        LDSM4(bfr[nxt][p], bb + bRowP[p] + ((kb + bkh) ^ cRow));
                    // distribute the chunk-fill burst over ks=0/1/2
                    // (slot slotF's previous readers finished at the PREVIOUS
                    //  iteration's ks=3 barrier)
                    if (ks == 0) {
#pragma unroll
                        for (int i = 0; i < 8; i++)
                            CP16(abF + i * 2048, sA + (size_t)i * 16 * DIN);
                    } else if (ks == 1) {
#pragma unroll
                        for (int i = 0; i < 4; i++)
                            CP16(bbF + i * 2048, sB + (size_t)i * 16 * DIN);
                    } else {
#pragma unroll
                        for (int i = 4; i < 8; i++)
                            CP16(bbF + i * 2048, sB + (size_t)i * 16 * DIN);
                    }
                } else {
                    CP_COMMIT();     // chunk it+2 group (uniform cadence)
                    CP_WAIT1();      // <=1 pending -> MY chunk it+1 copies done
                    __syncthreads(); // ALL threads' waits done -> chunk it+1
                                     // visible; also guards slot reuse
                    if (it + 1 < KCH) {
                        // cross-chunk prefetch of (it+1, ks=0) — now race-free
#pragma unroll
                        for (int mf = 0; mf < 4; mf++)
                            LDSM4(afr[nxt][mf], abn + aRow[mf] + (akh ^ cRow));
#pragma unroll
                        for (int p = 0; p < 4; p++)
                            LDSM4(bfr[nxt][p], bbn + bRowP[p] + (bkh ^ cRow));
                    }
                }
#pragma unroll
                for (int mf = 0; mf < 4; mf++)
#pragma unroll
                    for (int p = 0; p < 4; p++) {
                        HMMA(acc[mf][2 * p],     afr[cur][mf], bfr[cur][p][0], bfr[cur][p][1]);
                        HMMA(acc[mf][2 * p + 1], afr[cur][mf], bfr[cur][p][2], bfr[cur][p][3]);
                    }
            }
            slotC = slotN;
        }

        // tile epilogue: dequant + bias (scales/bias L2-resident), reset acc
        {
            const int bm = ti >> 5;
            const int bn = ti & 31;
            const float* swg = g_sw + bn * BN;
            const float* bg  = bias + bn * BN;
#pragma unroll
            for (int mf = 0; mf < 4; mf++) {
                const size_t gr0 = (size_t)bm * BM + wm * 64 + mf * 16 + qid;
                const float sx0 = g_sx[gr0];
                const float sx1 = g_sx[gr0 + 8];
                float* o0 = out + gr0 * DOUT + bn * BN;
                float* o1 = o0 + (size_t)8 * DOUT;
#pragma unroll
                for (int nf = 0; nf < 8; nf++) {
                    const int col = wn * 64 + nf * 8 + tc;
                    const float2 w2 = *reinterpret_cast<const float2*>(swg + col);
                    const float2 b2 = *reinterpret_cast<const float2*>(bg + col);
                    float2 v0, v1;
                    v0.x = acc[mf][nf][0] * (sx0 * w2.x) + b2.x;
                    v0.y = acc[mf][nf][1] * (sx0 * w2.y) + b2.y;
                    v1.x = acc[mf][nf][2] * (sx1 * w2.x) + b2.x;
                    v1.y = acc[mf][nf][3] * (sx1 * w2.y) + b2.y;
                    *reinterpret_cast<float2*>(o0 + col) = v0;
                    *reinterpret_cast<float2*>(o1 + col) = v1;
                    acc[mf][nf][0] = 0.f; acc[mf][nf][1] = 0.f;
                    acc[mf][nf][2] = 0.f; acc[mf][nf][3] = 0.f;
                }
            }
        }

        // advance to next tile; re-prefetch its ks=0 fragments from slotC.
        // chunk 64 is visible to ALL threads (wait + barrier at it=63 ks=3).
        ti = tiN; curA = nextA; curB = nextB;
        if (w + 1 < ntiles) {
            const uint32_t abC = sb + slotC * STAGE_BYTES;
            const uint32_t bbC = abC + A_BYTES;
#pragma unroll
            for (int mf = 0; mf < 4; mf++)
                LDSM4(afr[0][mf], abC + aRow[mf] + (akh ^ cRow));
#pragma unroll
            for (int p = 0; p < 4; p++)
                LDSM4(bfr[0][p], bbC + bRowP[p] + (bkh ^ cRow));
        }
    }
}

// ---------------- launch ----------------
extern "C" void kernel_launch(void* const* d_in, const int* in_sizes, int n_in,
                              void* d_out, int out_size) {
    const float* x    = (const float*)d_in[0];
    const float* W    = (const float*)d_in[1];
    const float* bias = (const float*)d_in[2];
    float* out        = (float*)d_out;

    quant_kernel<<<TOKENS + DOUT, 256>>>(x, W);

    cudaFuncSetAttribute(gemm_kernel, cudaFuncAttributeMaxDynamicSharedMemorySize, SMEM_TOTAL);
    gemm_kernel<<<NCTA, 128, SMEM_TOTAL>>>(bias, out);
}